// round 3
// baseline (speedup 1.0000x reference)
#include <cuda_runtime.h>
#include <math.h>

#define HID 1024

// Scratch tables produced by precompute, consumed by eval.
__device__ float g_t[HID];
__device__ float g_A0[HID + 1];
__device__ float g_B0[HID + 1];
__device__ float g_A1[HID + 1];
__device__ float g_B1[HID + 1];

__device__ __forceinline__ float softplusf(float z) {
    return fmaxf(z, 0.0f) + log1pf(expf(-fabsf(z)));
}

__device__ __forceinline__ double kl_term(double mu, double sigma, double ps) {
    double r = sigma / ps;
    double m = mu / ps;
    return 0.5 * (-2.0 * log(r) - 1.0 + r * r + m * m);
}

__global__ void __launch_bounds__(HID) precompute_kernel(
    const float* __restrict__ W1_mu, const float* __restrict__ W1_rho,
    const float* __restrict__ b1_mu, const float* __restrict__ b1_rho,
    const float* __restrict__ W2_mu, const float* __restrict__ W2_rho,
    const float* __restrict__ b2_mu, const float* __restrict__ b2_rho,
    const float* __restrict__ eps_W1, const float* __restrict__ eps_b1,
    const float* __restrict__ eps_W2, const float* __restrict__ eps_b2,
    float* __restrict__ kl_out)
{
    __shared__ float  s_t[HID];
    __shared__ int    s_idx[HID];
    __shared__ float  s_d0[HID];
    __shared__ float  s_d1[HID];
    __shared__ float  s_d2[HID];
    __shared__ float  s_d3[HID];
    __shared__ double s_red[HID];

    const int j = threadIdx.x;

    // Perturbed parameters for unit j
    const float sW1 = softplusf(W1_rho[j]);
    const float w   = W1_mu[j] + sW1 * eps_W1[j];
    const float sb1 = softplusf(b1_rho[j]);
    const float b   = b1_mu[j] + sb1 * eps_b1[j];
    const float sc0 = softplusf(W2_rho[j]);
    const float c0  = W2_mu[j] + sc0 * eps_W2[j];
    const float sc1 = softplusf(W2_rho[HID + j]);
    const float c1  = W2_mu[HID + j] + sc1 * eps_W2[HID + j];

    // Breakpoint + crossing deltas; baseline = active set at x -> -inf
    float t;
    float dA0, dB0, dA1, dB1;
    double bA0 = 0.0, bB0 = 0.0, bA1 = 0.0, bB1 = 0.0;
    if (w > 0.0f) {
        t = -b / w;
        dA0 = c0 * w;  dB0 = c0 * b;  dA1 = c1 * w;  dB1 = c1 * b;
    } else if (w < 0.0f) {
        t = -b / w;
        dA0 = -(c0 * w); dB0 = -(c0 * b); dA1 = -(c1 * w); dB1 = -(c1 * b);
        bA0 = (double)c0 * (double)w; bB0 = (double)c0 * (double)b;
        bA1 = (double)c1 * (double)w; bB1 = (double)c1 * (double)b;
    } else {
        t = INFINITY;
        dA0 = dB0 = dA1 = dB1 = 0.0f;
        if (b > 0.0f) { bB0 = (double)c0 * (double)b; bB1 = (double)c1 * (double)b; }
    }

    s_t[j] = t; s_idx[j] = j;
    s_d0[j] = dA0; s_d1[j] = dB0; s_d2[j] = dA1; s_d3[j] = dB1;
    __syncthreads();

    // Bitonic sort on breakpoint value with index payload
    for (int k = 2; k <= HID; k <<= 1) {
        for (int stp = k >> 1; stp > 0; stp >>= 1) {
            int ixj = j ^ stp;
            if (ixj > j) {
                bool up = ((j & k) == 0);
                float a = s_t[j], bb = s_t[ixj];
                if ((a > bb) == up) {
                    s_t[j] = bb; s_t[ixj] = a;
                    int tmp = s_idx[j]; s_idx[j] = s_idx[ixj]; s_idx[ixj] = tmp;
                }
            }
            __syncthreads();
        }
    }

    g_t[j] = s_t[j];
    const int src = s_idx[j];
    const float md0 = s_d0[src];
    const float md1 = s_d1[src];
    const float md2 = s_d2[src];
    const float md3 = s_d3[src];

    // KL (double-precision sums)
    const double PS1 = 4.0;
    const double PS2 = 2.25 / 32.0;   // 2.25 / sqrt(1024)
    double kl = kl_term(W1_mu[j],       sW1, PS1)
              + kl_term(b1_mu[j],       sb1, PS1)
              + kl_term(W2_mu[j],       sc0, PS2)
              + kl_term(W2_mu[HID + j], sc1, PS2);
    if (j < 2) kl += kl_term(b2_mu[j], softplusf(b2_rho[j]), PS2);

    // Block reductions: baselines + KL
    double vals[5] = {bA0, bB0, bA1, bB1, kl};
    double tot[5];
    for (int c = 0; c < 5; c++) {
        s_red[j] = vals[c];
        __syncthreads();
        for (int off = HID >> 1; off > 0; off >>= 1) {
            if (j < off) s_red[j] += s_red[j + off];
            __syncthreads();
        }
        tot[c] = s_red[0];
        __syncthreads();
    }
    if (j == 0) kl_out[0] = (float)tot[4];

    const float b2v0 = b2_mu[0] + softplusf(b2_rho[0]) * eps_b2[0];
    const float b2v1 = b2_mu[1] + softplusf(b2_rho[1]) * eps_b2[1];

    // Inclusive scans (double) of the 4 delta channels -> interval coefficients
    float  mds[4]   = {md0, md1, md2, md3};
    double bases[4] = {tot[0], tot[1] + (double)b2v0, tot[2], tot[3] + (double)b2v1};
    float* gout[4]  = {g_A0, g_B0, g_A1, g_B1};
    for (int c = 0; c < 4; c++) {
        s_red[j] = (double)mds[c];
        __syncthreads();
        for (int off = 1; off < HID; off <<= 1) {
            double v   = s_red[j];
            double add = (j >= off) ? s_red[j - off] : 0.0;
            __syncthreads();
            s_red[j] = v + add;
            __syncthreads();
        }
        double pre = s_red[j];
        if (j == 0) gout[c][0] = (float)bases[c];
        gout[c][j + 1] = (float)(bases[c] + pre);
        __syncthreads();
    }
}

__global__ void __launch_bounds__(256) eval_kernel(
    const float* __restrict__ x, float* __restrict__ out, int N)
{
    __shared__ float st[HID];
    __shared__ float sA0[HID + 1], sB0[HID + 1], sA1[HID + 1], sB1[HID + 1];

    for (int u = threadIdx.x; u < HID; u += 256) st[u] = g_t[u];
    for (int u = threadIdx.x; u < HID + 1; u += 256) {
        sA0[u] = g_A0[u]; sB0[u] = g_B0[u]; sA1[u] = g_A1[u]; sB1[u] = g_B1[u];
    }
    __syncthreads();

    int i = blockIdx.x * 256 + threadIdx.x;
    if (i < N) {
        float xv = x[i];
        // lower-bound binary search: m = #breakpoints <= xv
        int lo = 0, hi = HID;
        while (lo < hi) {
            int mid = (lo + hi) >> 1;
            if (st[mid] <= xv) lo = mid + 1; else hi = mid;
        }
        int m = lo;
        float mean = fmaf(sA0[m], xv, sB0[m]);
        float h    = fmaf(sA1[m], xv, sB1[m]);
        out[i] = mean;
        float sp = fmaxf(h, 0.0f) + log1pf(expf(-fabsf(h)));
        out[N + i] = 1e-5f + sp;
    }
}

extern "C" void kernel_launch(void* const* d_in, const int* in_sizes, int n_in,
                              void* d_out, int out_size) {
    const float* x      = (const float*)d_in[0];
    const float* W1_mu  = (const float*)d_in[1];
    const float* W1_rho = (const float*)d_in[2];
    const float* b1_mu  = (const float*)d_in[3];
    const float* b1_rho = (const float*)d_in[4];
    const float* W2_mu  = (const float*)d_in[5];
    const float* W2_rho = (const float*)d_in[6];
    const float* b2_mu  = (const float*)d_in[7];
    const float* b2_rho = (const float*)d_in[8];
    const float* eps_W1 = (const float*)d_in[9];
    const float* eps_b1 = (const float*)d_in[10];
    const float* eps_W2 = (const float*)d_in[11];
    const float* eps_b2 = (const float*)d_in[12];

    float* out = (float*)d_out;
    const int N = in_sizes[0];

    precompute_kernel<<<1, HID>>>(W1_mu, W1_rho, b1_mu, b1_rho,
                                  W2_mu, W2_rho, b2_mu, b2_rho,
                                  eps_W1, eps_b1, eps_W2, eps_b2,
                                  out + 2 * (size_t)N);

    int blocks = (N + 255) / 256;
    eval_kernel<<<blocks, 256>>>(x, out, N);
}

// round 4
// speedup vs baseline: 3.0154x; 3.0154x over previous
#include <cuda_runtime.h>
#include <math.h>

#define HID 1024
#define FULL 0xFFFFFFFFu

// Tables produced by precompute, consumed by eval.
__device__ float g_t[HID];
__device__ float g_A0[HID + 1];
__device__ float g_B0[HID + 1];
__device__ float g_A1[HID + 1];
__device__ float g_B1[HID + 1];

__device__ __forceinline__ float softplusf(float z) {
    return fmaxf(z, 0.0f) + log1pf(expf(-fabsf(z)));
}

__device__ __forceinline__ float kl_term_f(float mu, float sigma, float inv_ps) {
    float r = sigma * inv_ps;
    float m = mu * inv_ps;
    return 0.5f * (fmaf(r, r, -1.0f) + m * m - 2.0f * logf(r));
}

__global__ void __launch_bounds__(HID) precompute_kernel(
    const float* __restrict__ W1_mu, const float* __restrict__ W1_rho,
    const float* __restrict__ b1_mu, const float* __restrict__ b1_rho,
    const float* __restrict__ W2_mu, const float* __restrict__ W2_rho,
    const float* __restrict__ b2_mu, const float* __restrict__ b2_rho,
    const float* __restrict__ eps_W1, const float* __restrict__ eps_b1,
    const float* __restrict__ eps_W2, const float* __restrict__ eps_b2,
    float* __restrict__ kl_out)
{
    __shared__ float  s_t[HID];
    __shared__ int    s_idx[HID];
    __shared__ float  s_d0[HID];
    __shared__ float  s_d1[HID];
    __shared__ float  s_d2[HID];
    __shared__ float  s_d3[HID];
    __shared__ double s_ws[4][32];    // per-warp scan totals (4 channels)
    __shared__ double s_bw[4][32];    // per-warp baseline partials
    __shared__ float  s_kw[32];       // per-warp KL partials
    __shared__ double s_tot[4];
    __shared__ float  s_kl;

    const int j    = threadIdx.x;
    const int lane = j & 31;
    const int warp = j >> 5;

    // ---- Phase A: per-unit perturbed params, breakpoint, deltas, baseline, KL ----
    const float sW1 = softplusf(W1_rho[j]);
    const float w   = W1_mu[j] + sW1 * eps_W1[j];
    const float sb1 = softplusf(b1_rho[j]);
    const float b   = b1_mu[j] + sb1 * eps_b1[j];
    const float sc0 = softplusf(W2_rho[j]);
    const float c0  = W2_mu[j] + sc0 * eps_W2[j];
    const float sc1 = softplusf(W2_rho[HID + j]);
    const float c1  = W2_mu[HID + j] + sc1 * eps_W2[HID + j];

    float t, dA0, dB0, dA1, dB1;
    double bA0 = 0.0, bB0 = 0.0, bA1 = 0.0, bB1 = 0.0;
    if (w > 0.0f) {
        t = -b / w;
        dA0 = c0 * w;  dB0 = c0 * b;  dA1 = c1 * w;  dB1 = c1 * b;
    } else if (w < 0.0f) {
        t = -b / w;
        dA0 = -(c0 * w); dB0 = -(c0 * b); dA1 = -(c1 * w); dB1 = -(c1 * b);
        bA0 = (double)c0 * (double)w; bB0 = (double)c0 * (double)b;
        bA1 = (double)c1 * (double)w; bB1 = (double)c1 * (double)b;
    } else {
        t = INFINITY;
        dA0 = dB0 = dA1 = dB1 = 0.0f;
        if (b > 0.0f) { bB0 = (double)c0 * (double)b; bB1 = (double)c1 * (double)b; }
    }

    s_d0[j] = dA0; s_d1[j] = dB0; s_d2[j] = dA1; s_d3[j] = dB1;

    // KL in float (logf): warp-reduce now (no barrier needed yet)
    const float INV_PS1 = 0.25f;
    const float INV_PS2 = 32.0f / 2.25f;
    float kl = kl_term_f(W1_mu[j],       sW1, INV_PS1)
             + kl_term_f(b1_mu[j],       sb1, INV_PS1)
             + kl_term_f(W2_mu[j],       sc0, INV_PS2)
             + kl_term_f(W2_mu[HID + j], sc1, INV_PS2);
    if (j < 2) kl += kl_term_f(b2_mu[j], softplusf(b2_rho[j]), INV_PS2);

    // warp reductions for baselines (double) + kl (float)
    #pragma unroll
    for (int o = 16; o > 0; o >>= 1) {
        bA0 += __shfl_xor_sync(FULL, bA0, o);
        bB0 += __shfl_xor_sync(FULL, bB0, o);
        bA1 += __shfl_xor_sync(FULL, bA1, o);
        bB1 += __shfl_xor_sync(FULL, bB1, o);
        kl  += __shfl_xor_sync(FULL, kl, o);
    }
    if (lane == 0) {
        s_bw[0][warp] = bA0; s_bw[1][warp] = bB0;
        s_bw[2][warp] = bA1; s_bw[3][warp] = bB1;
        s_kw[warp] = kl;
    }

    // ---- Phase B: bitonic sort (t, idx). Registers + shuffles for strides<=16,
    //      shared for strides>=32. ----
    float my_t = t;
    int   my_i = j;

    // k = 2..32 : fully in-warp
    #pragma unroll
    for (int k = 2; k <= 32; k <<= 1) {
        const bool up = ((j & k) == 0);
        #pragma unroll
        for (int stp = k >> 1; stp > 0; stp >>= 1) {
            float o_t = __shfl_xor_sync(FULL, my_t, stp);
            int   o_i = __shfl_xor_sync(FULL, my_i, stp);
            bool lower = ((j & stp) == 0);
            float a = lower ? my_t : o_t;
            float bb = lower ? o_t : my_t;
            if ((a > bb) == up) { my_t = o_t; my_i = o_i; }
        }
    }

    // k = 64..1024 : shared steps for stride>=32, then in-warp tail
    #pragma unroll
    for (int k = 64; k <= HID; k <<= 1) {
        s_t[j] = my_t; s_idx[j] = my_i;
        __syncthreads();
        for (int stp = k >> 1; stp >= 32; stp >>= 1) {
            int ixj = j ^ stp;
            if (ixj > j) {
                bool up = ((j & k) == 0);
                float a = s_t[j], bb = s_t[ixj];
                if ((a > bb) == up) {
                    s_t[j] = bb; s_t[ixj] = a;
                    int ti = s_idx[j]; s_idx[j] = s_idx[ixj]; s_idx[ixj] = ti;
                }
            }
            __syncthreads();
        }
        my_t = s_t[j]; my_i = s_idx[j];
        const bool up = ((j & k) == 0);
        #pragma unroll
        for (int stp = 16; stp > 0; stp >>= 1) {
            float o_t = __shfl_xor_sync(FULL, my_t, stp);
            int   o_i = __shfl_xor_sync(FULL, my_i, stp);
            bool lower = ((j & stp) == 0);
            float a = lower ? my_t : o_t;
            float bb = lower ? o_t : my_t;
            if ((a > bb) == up) { my_t = o_t; my_i = o_i; }
        }
    }

    g_t[j] = my_t;

    // Gather this slot's deltas (phase-A shared writes are long since fenced by sort barriers)
    double v0 = (double)s_d0[my_i];
    double v1 = (double)s_d1[my_i];
    double v2 = (double)s_d2[my_i];
    double v3 = (double)s_d3[my_i];

    // ---- Phase C: 4-channel inclusive scan via shuffles ----
    #pragma unroll
    for (int o = 1; o < 32; o <<= 1) {
        double u0 = __shfl_up_sync(FULL, v0, o);
        double u1 = __shfl_up_sync(FULL, v1, o);
        double u2 = __shfl_up_sync(FULL, v2, o);
        double u3 = __shfl_up_sync(FULL, v3, o);
        if (lane >= o) { v0 += u0; v1 += u1; v2 += u2; v3 += u3; }
    }
    if (lane == 31) {
        s_ws[0][warp] = v0; s_ws[1][warp] = v1;
        s_ws[2][warp] = v2; s_ws[3][warp] = v3;
    }
    __syncthreads();

    // warp w (w<4) scans channel w's 32 warp-totals; warp 4 reduces baselines; warp 5 reduces kl
    if (warp < 4) {
        double v = s_ws[warp][lane];
        #pragma unroll
        for (int o = 1; o < 32; o <<= 1) {
            double u = __shfl_up_sync(FULL, v, o);
            if (lane >= o) v += u;
        }
        s_ws[warp][lane] = v;
    } else if (warp == 4) {
        if (lane < 4) {
            double v = 0.0;
            #pragma unroll
            for (int q = 0; q < 32; q++) v += s_bw[lane][q];
            s_tot[lane] = v;
        }
    } else if (warp == 5) {
        float v = (lane < 32) ? s_kw[lane] : 0.0f;
        #pragma unroll
        for (int o = 16; o > 0; o >>= 1) v += __shfl_xor_sync(FULL, v, o);
        if (lane == 0) s_kl = v;
    }
    __syncthreads();

    if (j == 0) kl_out[0] = s_kl;

    const float b2v0 = b2_mu[0] + softplusf(b2_rho[0]) * eps_b2[0];
    const float b2v1 = b2_mu[1] + softplusf(b2_rho[1]) * eps_b2[1];

    const double base0 = s_tot[0];
    const double base1 = s_tot[1] + (double)b2v0;
    const double base2 = s_tot[2];
    const double base3 = s_tot[3] + (double)b2v1;

    const double woff0 = (warp == 0) ? 0.0 : s_ws[0][warp - 1];
    const double woff1 = (warp == 0) ? 0.0 : s_ws[1][warp - 1];
    const double woff2 = (warp == 0) ? 0.0 : s_ws[2][warp - 1];
    const double woff3 = (warp == 0) ? 0.0 : s_ws[3][warp - 1];

    g_A0[j + 1] = (float)(base0 + woff0 + v0);
    g_B0[j + 1] = (float)(base1 + woff1 + v1);
    g_A1[j + 1] = (float)(base2 + woff2 + v2);
    g_B1[j + 1] = (float)(base3 + woff3 + v3);
    if (j == 0) {
        g_A0[0] = (float)base0;
        g_B0[0] = (float)base1;
        g_A1[0] = (float)base2;
        g_B1[0] = (float)base3;
    }
}

__global__ void __launch_bounds__(256) eval_kernel(
    const float* __restrict__ x, float* __restrict__ out, int N)
{
    __shared__ float st[HID];
    __shared__ float sA0[HID + 1], sB0[HID + 1], sA1[HID + 1], sB1[HID + 1];

    for (int u = threadIdx.x; u < HID; u += 256) st[u] = g_t[u];
    for (int u = threadIdx.x; u < HID + 1; u += 256) {
        sA0[u] = g_A0[u]; sB0[u] = g_B0[u]; sA1[u] = g_A1[u]; sB1[u] = g_B1[u];
    }
    __syncthreads();

    const int base = blockIdx.x * 1024 + threadIdx.x;

    float xv[4];
    int   m[4];
    bool  ok[4];
    #pragma unroll
    for (int u = 0; u < 4; u++) {
        int i = base + u * 256;
        ok[u] = (i < N);
        xv[u] = ok[u] ? x[i] : 0.0f;
        m[u] = 0;
    }

    // Branchless lower-bound, 4 interleaved searches (independent LDS chains)
    #pragma unroll
    for (int s = 512; s > 0; s >>= 1) {
        #pragma unroll
        for (int u = 0; u < 4; u++) {
            if (st[m[u] + s - 1] <= xv[u]) m[u] += s;
        }
    }
    #pragma unroll
    for (int u = 0; u < 4; u++) {
        if (st[m[u]] <= xv[u]) m[u] += 1;   // fixup: allows m == 1024
    }

    #pragma unroll
    for (int u = 0; u < 4; u++) {
        if (ok[u]) {
            int i = base + u * 256;
            float mean = fmaf(sA0[m[u]], xv[u], sB0[m[u]]);
            float h    = fmaf(sA1[m[u]], xv[u], sB1[m[u]]);
            out[i] = mean;
            float sp = fmaxf(h, 0.0f) + log1pf(expf(-fabsf(h)));
            out[N + i] = 1e-5f + sp;
        }
    }
}

extern "C" void kernel_launch(void* const* d_in, const int* in_sizes, int n_in,
                              void* d_out, int out_size) {
    const float* x      = (const float*)d_in[0];
    const float* W1_mu  = (const float*)d_in[1];
    const float* W1_rho = (const float*)d_in[2];
    const float* b1_mu  = (const float*)d_in[3];
    const float* b1_rho = (const float*)d_in[4];
    const float* W2_mu  = (const float*)d_in[5];
    const float* W2_rho = (const float*)d_in[6];
    const float* b2_mu  = (const float*)d_in[7];
    const float* b2_rho = (const float*)d_in[8];
    const float* eps_W1 = (const float*)d_in[9];
    const float* eps_b1 = (const float*)d_in[10];
    const float* eps_W2 = (const float*)d_in[11];
    const float* eps_b2 = (const float*)d_in[12];

    float* out = (float*)d_out;
    const int N = in_sizes[0];

    precompute_kernel<<<1, HID>>>(W1_mu, W1_rho, b1_mu, b1_rho,
                                  W2_mu, W2_rho, b2_mu, b2_rho,
                                  eps_W1, eps_b1, eps_W2, eps_b2,
                                  out + 2 * (size_t)N);

    int blocks = (N + 1023) / 1024;
    eval_kernel<<<blocks, 256>>>(x, out, N);
}

// round 5
// speedup vs baseline: 6.5955x; 2.1873x over previous
#include <cuda_runtime.h>
#include <math.h>

#define HID 1024
#define FULL 0xFFFFFFFFu

// Tables produced by precompute, consumed by eval.
__device__ float  g_t[HID];
__device__ float4 g_C[HID + 1];   // {A0, B0, A1, B1} per interval

__device__ __forceinline__ float softplusf(float z) {
    return fmaxf(z, 0.0f) + log1pf(expf(-fabsf(z)));
}

__device__ __forceinline__ float kl_term_f(float mu, float sigma, float inv_ps) {
    float r = sigma * inv_ps;
    float m = mu * inv_ps;
    return 0.5f * (fmaf(r, r, -1.0f) + m * m - 2.0f * logf(r));
}

__global__ void __launch_bounds__(HID) precompute_kernel(
    const float* __restrict__ W1_mu, const float* __restrict__ W1_rho,
    const float* __restrict__ b1_mu, const float* __restrict__ b1_rho,
    const float* __restrict__ W2_mu, const float* __restrict__ W2_rho,
    const float* __restrict__ b2_mu, const float* __restrict__ b2_rho,
    const float* __restrict__ eps_W1, const float* __restrict__ eps_b1,
    const float* __restrict__ eps_W2, const float* __restrict__ eps_b2,
    float* __restrict__ kl_out)
{
    __shared__ float s_t[HID];
    __shared__ int   s_idx[HID];
    __shared__ float s_d0[HID];
    __shared__ float s_d1[HID];
    __shared__ float s_d2[HID];
    __shared__ float s_d3[HID];
    __shared__ float s_ws[4][32];   // per-warp scan totals (4 channels)
    __shared__ float s_bw[4][32];   // per-warp baseline partials
    __shared__ float s_kw[32];      // per-warp KL partials
    __shared__ float s_tot[4];
    __shared__ float s_kl;

    const int j    = threadIdx.x;
    const int lane = j & 31;
    const int warp = j >> 5;

    // ---- Phase A: per-unit perturbed params, breakpoint, deltas, baseline, KL ----
    const float sW1 = softplusf(W1_rho[j]);
    const float w   = W1_mu[j] + sW1 * eps_W1[j];
    const float sb1 = softplusf(b1_rho[j]);
    const float b   = b1_mu[j] + sb1 * eps_b1[j];
    const float sc0 = softplusf(W2_rho[j]);
    const float c0  = W2_mu[j] + sc0 * eps_W2[j];
    const float sc1 = softplusf(W2_rho[HID + j]);
    const float c1  = W2_mu[HID + j] + sc1 * eps_W2[HID + j];

    float t, dA0, dB0, dA1, dB1;
    float bA0 = 0.0f, bB0 = 0.0f, bA1 = 0.0f, bB1 = 0.0f;
    if (w > 0.0f) {
        t = -b / w;
        dA0 = c0 * w;  dB0 = c0 * b;  dA1 = c1 * w;  dB1 = c1 * b;
    } else if (w < 0.0f) {
        t = -b / w;
        dA0 = -(c0 * w); dB0 = -(c0 * b); dA1 = -(c1 * w); dB1 = -(c1 * b);
        bA0 = c0 * w; bB0 = c0 * b; bA1 = c1 * w; bB1 = c1 * b;
    } else {
        t = INFINITY;
        dA0 = dB0 = dA1 = dB1 = 0.0f;
        if (b > 0.0f) { bB0 = c0 * b; bB1 = c1 * b; }
    }

    s_d0[j] = dA0; s_d1[j] = dB0; s_d2[j] = dA1; s_d3[j] = dB1;

    const float INV_PS1 = 0.25f;
    const float INV_PS2 = 32.0f / 2.25f;
    float kl = kl_term_f(W1_mu[j],       sW1, INV_PS1)
             + kl_term_f(b1_mu[j],       sb1, INV_PS1)
             + kl_term_f(W2_mu[j],       sc0, INV_PS2)
             + kl_term_f(W2_mu[HID + j], sc1, INV_PS2);
    if (j < 2) kl += kl_term_f(b2_mu[j], softplusf(b2_rho[j]), INV_PS2);

    // Warp reductions for baselines + kl (all float)
    #pragma unroll
    for (int o = 16; o > 0; o >>= 1) {
        bA0 += __shfl_xor_sync(FULL, bA0, o);
        bB0 += __shfl_xor_sync(FULL, bB0, o);
        bA1 += __shfl_xor_sync(FULL, bA1, o);
        bB1 += __shfl_xor_sync(FULL, bB1, o);
        kl  += __shfl_xor_sync(FULL, kl, o);
    }
    if (lane == 0) {
        s_bw[0][warp] = bA0; s_bw[1][warp] = bB0;
        s_bw[2][warp] = bA1; s_bw[3][warp] = bB1;
        s_kw[warp] = kl;
    }

    // ---- Phase B: bitonic sort (t, idx): shuffles for stride<=16, shared >=32 ----
    float my_t = t;
    int   my_i = j;

    #pragma unroll
    for (int k = 2; k <= 32; k <<= 1) {
        const bool up = ((j & k) == 0);
        #pragma unroll
        for (int stp = k >> 1; stp > 0; stp >>= 1) {
            float o_t = __shfl_xor_sync(FULL, my_t, stp);
            int   o_i = __shfl_xor_sync(FULL, my_i, stp);
            bool lower = ((j & stp) == 0);
            float a = lower ? my_t : o_t;
            float bb = lower ? o_t : my_t;
            if ((a > bb) == up) { my_t = o_t; my_i = o_i; }
        }
    }

    #pragma unroll
    for (int k = 64; k <= HID; k <<= 1) {
        s_t[j] = my_t; s_idx[j] = my_i;
        __syncthreads();
        for (int stp = k >> 1; stp >= 32; stp >>= 1) {
            int ixj = j ^ stp;
            if (ixj > j) {
                bool up = ((j & k) == 0);
                float a = s_t[j], bb = s_t[ixj];
                if ((a > bb) == up) {
                    s_t[j] = bb; s_t[ixj] = a;
                    int ti = s_idx[j]; s_idx[j] = s_idx[ixj]; s_idx[ixj] = ti;
                }
            }
            __syncthreads();
        }
        my_t = s_t[j]; my_i = s_idx[j];
        const bool up = ((j & k) == 0);
        #pragma unroll
        for (int stp = 16; stp > 0; stp >>= 1) {
            float o_t = __shfl_xor_sync(FULL, my_t, stp);
            int   o_i = __shfl_xor_sync(FULL, my_i, stp);
            bool lower = ((j & stp) == 0);
            float a = lower ? my_t : o_t;
            float bb = lower ? o_t : my_t;
            if ((a > bb) == up) { my_t = o_t; my_i = o_i; }
        }
    }

    g_t[j] = my_t;

    // Gather this slot's deltas (sorted order)
    float v0 = s_d0[my_i];
    float v1 = s_d1[my_i];
    float v2 = s_d2[my_i];
    float v3 = s_d3[my_i];

    // ---- Phase C: 4-channel inclusive warp scan (float shuffles) ----
    #pragma unroll
    for (int o = 1; o < 32; o <<= 1) {
        float u0 = __shfl_up_sync(FULL, v0, o);
        float u1 = __shfl_up_sync(FULL, v1, o);
        float u2 = __shfl_up_sync(FULL, v2, o);
        float u3 = __shfl_up_sync(FULL, v3, o);
        if (lane >= o) { v0 += u0; v1 += u1; v2 += u2; v3 += u3; }
    }
    if (lane == 31) {
        s_ws[0][warp] = v0; s_ws[1][warp] = v1;
        s_ws[2][warp] = v2; s_ws[3][warp] = v3;
    }
    __syncthreads();

    // warps 0-3: scan one channel's warp totals; warps 4-7: reduce one baseline
    // channel; warp 8: reduce KL. All shuffle-parallel.
    if (warp < 4) {
        float v = s_ws[warp][lane];
        #pragma unroll
        for (int o = 1; o < 32; o <<= 1) {
            float u = __shfl_up_sync(FULL, v, o);
            if (lane >= o) v += u;
        }
        s_ws[warp][lane] = v;
    } else if (warp < 8) {
        float v = s_bw[warp - 4][lane];
        #pragma unroll
        for (int o = 16; o > 0; o >>= 1) v += __shfl_xor_sync(FULL, v, o);
        if (lane == 0) s_tot[warp - 4] = v;
    } else if (warp == 8) {
        float v = s_kw[lane];
        #pragma unroll
        for (int o = 16; o > 0; o >>= 1) v += __shfl_xor_sync(FULL, v, o);
        if (lane == 0) s_kl = v;
    }
    __syncthreads();

    if (j == 0) kl_out[0] = s_kl;

    const float b2v0 = b2_mu[0] + softplusf(b2_rho[0]) * eps_b2[0];
    const float b2v1 = b2_mu[1] + softplusf(b2_rho[1]) * eps_b2[1];

    const float base0 = s_tot[0];
    const float base1 = s_tot[1] + b2v0;
    const float base2 = s_tot[2];
    const float base3 = s_tot[3] + b2v1;

    const float woff0 = (warp == 0) ? 0.0f : s_ws[0][warp - 1];
    const float woff1 = (warp == 0) ? 0.0f : s_ws[1][warp - 1];
    const float woff2 = (warp == 0) ? 0.0f : s_ws[2][warp - 1];
    const float woff3 = (warp == 0) ? 0.0f : s_ws[3][warp - 1];

    float4 c;
    c.x = base0 + woff0 + v0;
    c.y = base1 + woff1 + v1;
    c.z = base2 + woff2 + v2;
    c.w = base3 + woff3 + v3;
    g_C[j + 1] = c;
    if (j == 0) g_C[0] = make_float4(base0, base1, base2, base3);
}

__global__ void __launch_bounds__(256) eval_kernel(
    const float* __restrict__ x, float* __restrict__ out, int N)
{
    __shared__ float  st[HID];
    __shared__ float4 sC[HID + 1];

    const int base = blockIdx.x * 512 + threadIdx.x;

    // Prefetch x before the barrier to hide global latency
    float xv0 = 0.0f, xv1 = 0.0f;
    const bool ok0 = (base < N);
    const bool ok1 = (base + 256 < N);
    if (ok0) xv0 = __ldg(x + base);
    if (ok1) xv1 = __ldg(x + base + 256);

    // Fill tables (vectorized coefficient loads)
    {
        const float4* gt4 = (const float4*)g_t;
        float4* st4 = (float4*)st;
        for (int u = threadIdx.x; u < HID / 4; u += 256) st4[u] = gt4[u];
        for (int u = threadIdx.x; u < HID + 1; u += 256) sC[u] = g_C[u];
    }
    __syncthreads();

    // Branchless lower-bound, 2 interleaved searches
    int m0 = 0, m1 = 0;
    #pragma unroll
    for (int s = 512; s > 0; s >>= 1) {
        if (st[m0 + s - 1] <= xv0) m0 += s;
        if (st[m1 + s - 1] <= xv1) m1 += s;
    }
    if (st[m0] <= xv0) m0 += 1;
    if (st[m1] <= xv1) m1 += 1;

    if (ok0) {
        float4 c = sC[m0];
        out[base] = fmaf(c.x, xv0, c.y);
        float h = fmaf(c.z, xv0, c.w);
        out[N + base] = 1e-5f + fmaxf(h, 0.0f) + log1pf(expf(-fabsf(h)));
    }
    if (ok1) {
        float4 c = sC[m1];
        out[base + 256] = fmaf(c.x, xv1, c.y);
        float h = fmaf(c.z, xv1, c.w);
        out[N + base + 256] = 1e-5f + fmaxf(h, 0.0f) + log1pf(expf(-fabsf(h)));
    }
}

extern "C" void kernel_launch(void* const* d_in, const int* in_sizes, int n_in,
                              void* d_out, int out_size) {
    const float* x      = (const float*)d_in[0];
    const float* W1_mu  = (const float*)d_in[1];
    const float* W1_rho = (const float*)d_in[2];
    const float* b1_mu  = (const float*)d_in[3];
    const float* b1_rho = (const float*)d_in[4];
    const float* W2_mu  = (const float*)d_in[5];
    const float* W2_rho = (const float*)d_in[6];
    const float* b2_mu  = (const float*)d_in[7];
    const float* b2_rho = (const float*)d_in[8];
    const float* eps_W1 = (const float*)d_in[9];
    const float* eps_b1 = (const float*)d_in[10];
    const float* eps_W2 = (const float*)d_in[11];
    const float* eps_b2 = (const float*)d_in[12];

    float* out = (float*)d_out;
    const int N = in_sizes[0];

    precompute_kernel<<<1, HID>>>(W1_mu, W1_rho, b1_mu, b1_rho,
                                  W2_mu, W2_rho, b2_mu, b2_rho,
                                  eps_W1, eps_b1, eps_W2, eps_b2,
                                  out + 2 * (size_t)N);

    int blocks = (N + 511) / 512;
    eval_kernel<<<blocks, 256>>>(x, out, N);
}